// round 2
// baseline (speedup 1.0000x reference)
#include <cuda_runtime.h>
#include <cstdint>

// Problem shape (fixed per reference):
//   B=32, N=4096, E=8192, D=128
//   atom_state (B,N,D) f32 ; messages (B,E,D) f32 ; connectivity (B,E,2) i32
//   kernel (D,3D) f32 ; recurrent_kernel (D,3D) f32 ; bias (2,3D) f32
//   out (B,N,D) f32
#define BB   32
#define NN   4096
#define EE   8192
#define DD   128
#define MM   (BB * NN)          // 131072 rows
#define NEDGE (BB * EE)         // 262144 edges

// 64MB aggregation scratch (allowed: __device__ global, no runtime alloc)
__device__ float g_agg[(size_t)MM * DD];

// ---------------------------------------------------------------------------
// helpers
// ---------------------------------------------------------------------------
__device__ __forceinline__ uint32_t f2tf32(float x) {
    uint32_t r;
    asm("cvt.rna.tf32.f32 %0, %1;" : "=r"(r) : "f"(x));
    return r;
}

__device__ __forceinline__ float sigmoidf_fast(float x) {
    return 1.0f / (1.0f + __expf(-x));
}

// overflow-safe fast tanh via exp (uses |x| so __expf never overflows)
__device__ __forceinline__ float tanh_safe(float x) {
    float e = __expf(-2.0f * fabsf(x));
    float t = (1.0f - e) / (1.0f + e);
    return copysignf(t, x);
}

__device__ __forceinline__ void mma_tf32(float c[4], const uint32_t a[4], const uint32_t b[2]) {
    asm volatile(
        "mma.sync.aligned.m16n8k8.row.col.f32.tf32.tf32.f32 "
        "{%0,%1,%2,%3}, {%4,%5,%6,%7}, {%8,%9}, {%0,%1,%2,%3};\n"
        : "+f"(c[0]), "+f"(c[1]), "+f"(c[2]), "+f"(c[3])
        : "r"(a[0]), "r"(a[1]), "r"(a[2]), "r"(a[3]),
          "r"(b[0]), "r"(b[1]));
}

// ---------------------------------------------------------------------------
// kernel 1: zero the aggregation scratch
// ---------------------------------------------------------------------------
__global__ void zero_agg_kernel() {
    const size_t n4 = (size_t)MM * DD / 4;   // 4,194,304 float4
    float4* p = reinterpret_cast<float4*>(g_agg);
    for (size_t i = (size_t)blockIdx.x * blockDim.x + threadIdx.x;
         i < n4;
         i += (size_t)gridDim.x * blockDim.x) {
        p[i] = make_float4(0.f, 0.f, 0.f, 0.f);
    }
}

// ---------------------------------------------------------------------------
// kernel 2: scatter-add messages into g_agg (segment_sum over target index)
// one warp per edge, one float4 vector-reduction per lane
// ---------------------------------------------------------------------------
__global__ void scatter_kernel(const float* __restrict__ msgs,
                               const int*   __restrict__ conn) {
    const int gwarp = (blockIdx.x * blockDim.x + threadIdx.x) >> 5;
    const int lane  = threadIdx.x & 31;
    if (gwarp >= NEDGE) return;

    const int tgt = __ldg(&conn[2 * gwarp + 1]);   // connectivity[b, e, 1]
    const int b   = gwarp >> 13;                   // gwarp / EE  (EE = 8192)

    const float4 m = reinterpret_cast<const float4*>(msgs)[(size_t)gwarp * 32 + lane];
    float* dst = &g_agg[((size_t)b * NN + tgt) * DD + lane * 4];
    asm volatile("red.global.add.v4.f32 [%0], {%1, %2, %3, %4};"
                 :: "l"(dst), "f"(m.x), "f"(m.y), "f"(m.z), "f"(m.w)
                 : "memory");
}

// ---------------------------------------------------------------------------
// kernel 3: fused dual-GEMM + GRU gates
//   per block: 64 rows; X = agg@W (3 chunks of 128 cols, kept in 96 regs)
//   then H = h@U chunk-by-chunk in order r -> z -> hh, gates fused, out written
// ---------------------------------------------------------------------------
// smem layout (bytes):
//   sA1 : [64][132] u32 (tf32 agg tile)   = 33792
//   sA2 : [64][132] f32 (exact h tile)    = 33792
//   sB  : [128][136] u32 (tf32 weight chunk) = 69632
#define SA_PAD 132
#define SB_PAD 136
#define SMEM_BYTES (64*SA_PAD*4 + 64*SA_PAD*4 + 128*SB_PAD*4)

__device__ __forceinline__ void load_B_chunk(uint32_t* __restrict__ sB,
                                             const float* __restrict__ W,
                                             int q, int tid) {
#pragma unroll
    for (int idx = tid; idx < 128 * 32; idx += 256) {
        const int r  = idx >> 5;
        const int c4 = (idx & 31) << 2;
        float4 v = *reinterpret_cast<const float4*>(&W[r * 384 + q * 128 + c4]);
        uint4 t = make_uint4(f2tf32(v.x), f2tf32(v.y), f2tf32(v.z), f2tf32(v.w));
        *reinterpret_cast<uint4*>(&sB[r * SB_PAD + c4]) = t;
    }
}

template <bool FROM_TF32>
__device__ __forceinline__ void gemm_chunk(float* __restrict__ acc,           // [32]
                                           const uint32_t* __restrict__ sA_t,
                                           const float*    __restrict__ sA_f,
                                           const uint32_t* __restrict__ sB,
                                           int warpM, int warpN, int gID, int tig) {
#pragma unroll
    for (int ks = 0; ks < 16; ks++) {
        const int k0 = ks * 8;
        uint32_t a[2][4];
#pragma unroll
        for (int i = 0; i < 2; i++) {
            const int r = warpM * 32 + i * 16 + gID;
            if (FROM_TF32) {
                a[i][0] = sA_t[r * SA_PAD + k0 + tig];
                a[i][1] = sA_t[(r + 8) * SA_PAD + k0 + tig];
                a[i][2] = sA_t[r * SA_PAD + k0 + tig + 4];
                a[i][3] = sA_t[(r + 8) * SA_PAD + k0 + tig + 4];
            } else {
                a[i][0] = f2tf32(sA_f[r * SA_PAD + k0 + tig]);
                a[i][1] = f2tf32(sA_f[(r + 8) * SA_PAD + k0 + tig]);
                a[i][2] = f2tf32(sA_f[r * SA_PAD + k0 + tig + 4]);
                a[i][3] = f2tf32(sA_f[(r + 8) * SA_PAD + k0 + tig + 4]);
            }
        }
        uint32_t b[4][2];
#pragma unroll
        for (int j = 0; j < 4; j++) {
            const int cc = warpN * 32 + j * 8 + gID;
            b[j][0] = sB[(k0 + tig) * SB_PAD + cc];
            b[j][1] = sB[(k0 + tig + 4) * SB_PAD + cc];
        }
#pragma unroll
        for (int i = 0; i < 2; i++)
#pragma unroll
            for (int j = 0; j < 4; j++)
                mma_tf32(&acc[(i * 4 + j) * 4], a[i], b[j]);
    }
}

__global__ __launch_bounds__(256, 1)
void fused_gru_kernel(const float* __restrict__ atom_state,
                      const float* __restrict__ Wk,
                      const float* __restrict__ Uk,
                      const float* __restrict__ bias,
                      float* __restrict__ out) {
    extern __shared__ unsigned char smem_raw[];
    uint32_t* sA1 = reinterpret_cast<uint32_t*>(smem_raw);
    float*    sA2 = reinterpret_cast<float*>(smem_raw + 64 * SA_PAD * 4);
    uint32_t* sB  = reinterpret_cast<uint32_t*>(smem_raw + 2 * 64 * SA_PAD * 4);

    const int tid   = threadIdx.x;
    const int lane  = tid & 31;
    const int warp  = tid >> 5;
    const int warpM = warp >> 2;   // 0..1  (32-row slice)
    const int warpN = warp & 3;    // 0..3  (32-col slice)
    const int gID   = lane >> 2;   // 0..7
    const int tig   = lane & 3;    // 0..3
    const int row0  = blockIdx.x * 64;

    // ---- load A tiles: agg -> tf32 smem, h -> exact f32 smem ----
#pragma unroll
    for (int idx = tid; idx < 64 * 32; idx += 256) {
        const int r  = idx >> 5;
        const int c4 = (idx & 31) << 2;
        const size_t g = (size_t)(row0 + r) * DD + c4;
        float4 va = *reinterpret_cast<const float4*>(&g_agg[g]);
        float4 vh = *reinterpret_cast<const float4*>(&atom_state[g]);
        uint4 ta = make_uint4(f2tf32(va.x), f2tf32(va.y), f2tf32(va.z), f2tf32(va.w));
        *reinterpret_cast<uint4*>(&sA1[r * SA_PAD + c4]) = ta;
        *reinterpret_cast<float4*>(&sA2[r * SA_PAD + c4]) = vh;
    }

    // ---- GEMM 1: X = agg @ W, three 128-col chunks kept in registers ----
    float X[3][32];
#pragma unroll
    for (int q = 0; q < 3; q++)
#pragma unroll
        for (int u = 0; u < 32; u++) X[q][u] = 0.f;

#pragma unroll
    for (int q = 0; q < 3; q++) {
        __syncthreads();                 // also covers the A-tile loads on q==0
        load_B_chunk(sB, Wk, q, tid);
        __syncthreads();
        gemm_chunk<true>(X[q], sA1, nullptr, sB, warpM, warpN, gID, tig);
    }

    float Hc[32];

    // ---- U chunk 1 -> r (stored into X[1]) ----
    __syncthreads();
    load_B_chunk(sB, Uk, 1, tid);
    __syncthreads();
#pragma unroll
    for (int u = 0; u < 32; u++) Hc[u] = 0.f;
    gemm_chunk<false>(Hc, nullptr, sA2, sB, warpM, warpN, gID, tig);
#pragma unroll
    for (int i = 0; i < 2; i++)
#pragma unroll
        for (int j = 0; j < 4; j++)
#pragma unroll
            for (int c = 0; c < 4; c++) {
                const int u   = (i * 4 + j) * 4 + c;
                const int col = warpN * 32 + j * 8 + tig * 2 + (c & 1);
                const float v = X[1][u] + bias[128 + col] + Hc[u] + bias[384 + 128 + col];
                X[1][u] = sigmoidf_fast(v);          // r gate
            }

    // ---- U chunk 0 -> z (stored into X[0]) ----
    __syncthreads();
    load_B_chunk(sB, Uk, 0, tid);
    __syncthreads();
#pragma unroll
    for (int u = 0; u < 32; u++) Hc[u] = 0.f;
    gemm_chunk<false>(Hc, nullptr, sA2, sB, warpM, warpN, gID, tig);
#pragma unroll
    for (int i = 0; i < 2; i++)
#pragma unroll
        for (int j = 0; j < 4; j++)
#pragma unroll
            for (int c = 0; c < 4; c++) {
                const int u   = (i * 4 + j) * 4 + c;
                const int col = warpN * 32 + j * 8 + tig * 2 + (c & 1);
                const float v = X[0][u] + bias[col] + Hc[u] + bias[384 + col];
                X[0][u] = sigmoidf_fast(v);          // z gate
            }

    // ---- U chunk 2 -> hh, combine, write out ----
    __syncthreads();
    load_B_chunk(sB, Uk, 2, tid);
    __syncthreads();
#pragma unroll
    for (int u = 0; u < 32; u++) Hc[u] = 0.f;
    gemm_chunk<false>(Hc, nullptr, sA2, sB, warpM, warpN, gID, tig);
#pragma unroll
    for (int i = 0; i < 2; i++)
#pragma unroll
        for (int j = 0; j < 4; j++)
#pragma unroll
            for (int c = 0; c < 4; c++) {
                const int u   = (i * 4 + j) * 4 + c;
                const int rt  = warpM * 32 + i * 16 + gID + ((c >> 1) << 3);
                const int col = warpN * 32 + j * 8 + tig * 2 + (c & 1);
                const float rh = Hc[u] + bias[384 + 256 + col];
                const float hh = tanh_safe(X[2][u] + bias[256 + col] + X[1][u] * rh);
                const float z  = X[0][u];
                const float h  = sA2[rt * SA_PAD + col];   // exact fp32 h
                out[(size_t)(row0 + rt) * DD + col] = z * h + (1.0f - z) * hh;
            }
}

// ---------------------------------------------------------------------------
// launch
// ---------------------------------------------------------------------------
extern "C" void kernel_launch(void* const* d_in, const int* in_sizes, int n_in,
                              void* d_out, int out_size) {
    const float* atom_state = (const float*)d_in[0];
    const float* messages   = (const float*)d_in[1];
    const int*   conn       = (const int*)d_in[2];
    const float* Wk         = (const float*)d_in[3];
    const float* Uk         = (const float*)d_in[4];
    const float* bias       = (const float*)d_in[5];
    float*       out        = (float*)d_out;
    (void)in_sizes; (void)n_in; (void)out_size;

    cudaFuncSetAttribute(fused_gru_kernel,
                         cudaFuncAttributeMaxDynamicSharedMemorySize, SMEM_BYTES);

    zero_agg_kernel<<<4096, 256>>>();
    scatter_kernel<<<NEDGE / 8, 256>>>(messages, conn);   // 8 warps/block
    fused_gru_kernel<<<MM / 64, 256, SMEM_BYTES>>>(atom_state, Wk, Uk, bias, out);
}

// round 3
// speedup vs baseline: 1.1046x; 1.1046x over previous
#include <cuda_runtime.h>
#include <cstdint>

// Problem shape (fixed per reference):
//   B=32, N=4096, E=8192, D=128
#define BB   32
#define NN   4096
#define EE   8192
#define DD   128
#define MM   (BB * NN)          // 131072 rows
#define NEDGE (BB * EE)         // 262144 edges

// 64MB aggregation scratch + 384KB tf32 weight scratch (device globals, no alloc)
__device__ float    g_agg[(size_t)MM * DD];
__device__ uint32_t g_Btf[2 * 3 * 128 * 128];   // [m][q][k][c] chunk-major tf32

// ---------------------------------------------------------------------------
// helpers
// ---------------------------------------------------------------------------
__device__ __forceinline__ uint32_t f2tf32(float x) {
    uint32_t r;
    asm("cvt.rna.tf32.f32 %0, %1;" : "=r"(r) : "f"(x));
    return r;
}

__device__ __forceinline__ float sigmoidf_fast(float x) {
    return 1.0f / (1.0f + __expf(-x));
}

__device__ __forceinline__ float tanh_safe(float x) {
    float e = __expf(-2.0f * fabsf(x));
    float t = (1.0f - e) / (1.0f + e);
    return copysignf(t, x);
}

__device__ __forceinline__ void mma_tf32(float c[4], const uint32_t a[4], const uint32_t b[2]) {
    asm volatile(
        "mma.sync.aligned.m16n8k8.row.col.f32.tf32.tf32.f32 "
        "{%0,%1,%2,%3}, {%4,%5,%6,%7}, {%8,%9}, {%0,%1,%2,%3};\n"
        : "+f"(c[0]), "+f"(c[1]), "+f"(c[2]), "+f"(c[3])
        : "r"(a[0]), "r"(a[1]), "r"(a[2]), "r"(a[3]),
          "r"(b[0]), "r"(b[1]));
}

__device__ __forceinline__ void cp_async16(uint32_t smem_addr, const void* gptr) {
    asm volatile("cp.async.cg.shared.global [%0], [%1], 16;\n"
                 :: "r"(smem_addr), "l"(gptr));
}

// ---------------------------------------------------------------------------
// kernel: convert W and U to chunk-major tf32 scratch
//   g_Btf[((m*3+q)*128 + k)*128 + c] = tf32( (m?U:W)[k*384 + q*128 + c] )
// ---------------------------------------------------------------------------
__global__ void convert_B_kernel(const float* __restrict__ W,
                                 const float* __restrict__ U) {
    const int idx = blockIdx.x * blockDim.x + threadIdx.x;   // 0..24575 (x float4)
    if (idx >= 2 * 3 * 128 * 32) return;
    const int c4  = (idx & 31) << 2;
    const int k   = (idx >> 5) & 127;
    const int rest = idx >> 12;          // 0..5
    const int m   = rest / 3;
    const int q   = rest % 3;
    const float* src = m ? U : W;
    float4 v = *reinterpret_cast<const float4*>(&src[k * 384 + q * 128 + c4]);
    uint4 t = make_uint4(f2tf32(v.x), f2tf32(v.y), f2tf32(v.z), f2tf32(v.w));
    *reinterpret_cast<uint4*>(&g_Btf[((m * 3 + q) * 128 + k) * 128 + c4]) = t;
}

// ---------------------------------------------------------------------------
// kernel: scatter-add messages into g_agg (one warp per edge, red.v4)
// ---------------------------------------------------------------------------
__global__ void scatter_kernel(const float* __restrict__ msgs,
                               const int*   __restrict__ conn) {
    const int gwarp = (blockIdx.x * blockDim.x + threadIdx.x) >> 5;
    const int lane  = threadIdx.x & 31;
    if (gwarp >= NEDGE) return;

    const int tgt = __ldg(&conn[2 * gwarp + 1]);
    const int b   = gwarp >> 13;                   // / EE

    const float4 m = reinterpret_cast<const float4*>(msgs)[(size_t)gwarp * 32 + lane];
    float* dst = &g_agg[((size_t)b * NN + tgt) * DD + lane * 4];
    asm volatile("red.global.add.v4.f32 [%0], {%1, %2, %3, %4};"
                 :: "l"(dst), "f"(m.x), "f"(m.y), "f"(m.z), "f"(m.w)
                 : "memory");
}

// ---------------------------------------------------------------------------
// fused dual-GEMM + GRU gates, cp.async double-buffered pipeline
//   12 stages: (GEMM1 q=0,1,2) x (k-half 0,1), then (GEMM2 q=1,0,2) x (half)
// ---------------------------------------------------------------------------
#define SA_PAD 132
#define SB_PAD 136
// sA1 tf32 agg [64][132], sA2 f32 h [64][132], sB[2][64][136]
#define SA_BYTES (64 * SA_PAD * 4)
#define SBBUF_BYTES (64 * SB_PAD * 4)
#define SMEM_BYTES (2 * SA_BYTES + 2 * SBBUF_BYTES)

__host__ __device__ constexpr int stage_gbase(int s) {
    // m=0: q = s/2 ; m=1 (s>=6): q order {1,0,2}
    int m = (s < 6) ? 0 : 1;
    int qi = (m == 0) ? (s >> 1) : ((s - 6) >> 1);
    int q = (m == 0) ? qi : (qi == 0 ? 1 : (qi == 1 ? 0 : 2));
    int h = s & 1;
    return ((m * 3 + q) * 128 + h * 64) * 128;
}

__device__ __forceinline__ void issue_load(uint32_t sdst, int gbase, int tid) {
#pragma unroll
    for (int i = 0; i < 8; i++) {
        const int idx = tid + i * 256;           // 0..2047
        const int row = idx >> 5;                // 0..63
        const int c4  = (idx & 31) << 2;         // 0..124
        cp_async16(sdst + (uint32_t)(row * SB_PAD + c4) * 4,
                   &g_Btf[gbase + row * 128 + c4]);
    }
}

template <bool FROM_TF32>
__device__ __forceinline__ void compute_half(float* __restrict__ acc,          // [32]
                                             const uint32_t* __restrict__ sA_t,
                                             const float*    __restrict__ sA_f,
                                             const uint32_t* __restrict__ sB,
                                             int kbase,
                                             int warpM, int warpN, int gID, int tig) {
#pragma unroll
    for (int ks = 0; ks < 8; ks++) {
        const int k0 = kbase + ks * 8;           // A column base (global k)
        const int bk = ks * 8 + tig;             // B row base (local to half)
        uint32_t a[2][4];
#pragma unroll
        for (int i = 0; i < 2; i++) {
            const int r = warpM * 32 + i * 16 + gID;
            if (FROM_TF32) {
                a[i][0] = sA_t[r * SA_PAD + k0 + tig];
                a[i][1] = sA_t[(r + 8) * SA_PAD + k0 + tig];
                a[i][2] = sA_t[r * SA_PAD + k0 + tig + 4];
                a[i][3] = sA_t[(r + 8) * SA_PAD + k0 + tig + 4];
            } else {
                a[i][0] = f2tf32(sA_f[r * SA_PAD + k0 + tig]);
                a[i][1] = f2tf32(sA_f[(r + 8) * SA_PAD + k0 + tig]);
                a[i][2] = f2tf32(sA_f[r * SA_PAD + k0 + tig + 4]);
                a[i][3] = f2tf32(sA_f[(r + 8) * SA_PAD + k0 + tig + 4]);
            }
        }
        uint32_t b[4][2];
#pragma unroll
        for (int j = 0; j < 4; j++) {
            const int cc = warpN * 32 + j * 8 + gID;
            b[j][0] = sB[bk * SB_PAD + cc];
            b[j][1] = sB[(bk + 4) * SB_PAD + cc];
        }
#pragma unroll
        for (int i = 0; i < 2; i++)
#pragma unroll
            for (int j = 0; j < 4; j++)
                mma_tf32(&acc[(i * 4 + j) * 4], a[i], b[j]);
    }
}

// STAGE: prefetch stage s+1 (if any), wait for s, compute s on accumulator ACC.
#define STAGE(s, ACC, FT)                                                          \
    {                                                                              \
        if ((s) + 1 < 12) {                                                        \
            issue_load(sb_addr[((s) + 1) & 1], stage_gbase((s) + 1), tid);         \
            asm volatile("cp.async.commit_group;");                                \
        }                                                                          \
        asm volatile("cp.async.wait_group %0;" :: "n"((((s) + 1) < 12) ? 1 : 0));  \
        __syncthreads();                                                           \
        compute_half<FT>(ACC, sA1, sA2, sBbuf[(s) & 1], ((s) & 1) * 64,            \
                         warpM, warpN, gID, tig);                                  \
        __syncthreads();                                                           \
    }

__global__ __launch_bounds__(256, 1)
void fused_gru_kernel(const float* __restrict__ atom_state,
                      const float* __restrict__ bias,
                      float* __restrict__ out) {
    extern __shared__ unsigned char smem_raw[];
    uint32_t* sA1 = reinterpret_cast<uint32_t*>(smem_raw);
    float*    sA2 = reinterpret_cast<float*>(smem_raw + SA_BYTES);
    uint32_t* sBbuf[2];
    sBbuf[0] = reinterpret_cast<uint32_t*>(smem_raw + 2 * SA_BYTES);
    sBbuf[1] = reinterpret_cast<uint32_t*>(smem_raw + 2 * SA_BYTES + SBBUF_BYTES);
    uint32_t sb_addr[2];
    sb_addr[0] = (uint32_t)__cvta_generic_to_shared(sBbuf[0]);
    sb_addr[1] = (uint32_t)__cvta_generic_to_shared(sBbuf[1]);

    const int tid   = threadIdx.x;
    const int lane  = tid & 31;
    const int warp  = tid >> 5;
    const int warpM = warp >> 2;   // 0..1
    const int warpN = warp & 3;    // 0..3
    const int gID   = lane >> 2;   // 0..7
    const int tig   = lane & 3;    // 0..3
    const int row0  = blockIdx.x * 64;

    // prefetch stage 0 while we load A tiles
    issue_load(sb_addr[0], stage_gbase(0), tid);
    asm volatile("cp.async.commit_group;");

    // ---- A tiles: agg -> tf32 smem, h -> exact f32 smem ----
#pragma unroll
    for (int idx = tid; idx < 64 * 32; idx += 256) {
        const int r  = idx >> 5;
        const int c4 = (idx & 31) << 2;
        const size_t g = (size_t)(row0 + r) * DD + c4;
        float4 va = *reinterpret_cast<const float4*>(&g_agg[g]);
        float4 vh = *reinterpret_cast<const float4*>(&atom_state[g]);
        uint4 ta = make_uint4(f2tf32(va.x), f2tf32(va.y), f2tf32(va.z), f2tf32(va.w));
        *reinterpret_cast<uint4*>(&sA1[r * SA_PAD + c4]) = ta;
        *reinterpret_cast<float4*>(&sA2[r * SA_PAD + c4]) = vh;
    }

    // ---- GEMM 1: X = agg @ W  (stages 0..5) ----
    float X[3][32];
#pragma unroll
    for (int q = 0; q < 3; q++)
#pragma unroll
        for (int u = 0; u < 32; u++) X[q][u] = 0.f;

    STAGE(0, X[0], true)
    STAGE(1, X[0], true)
    STAGE(2, X[1], true)
    STAGE(3, X[1], true)
    STAGE(4, X[2], true)
    STAGE(5, X[2], true)

    float Hc[32];

    // ---- GEMM 2 chunk r (U q=1), stages 6,7 ----
#pragma unroll
    for (int u = 0; u < 32; u++) Hc[u] = 0.f;
    STAGE(6, Hc, false)
    STAGE(7, Hc, false)
#pragma unroll
    for (int i = 0; i < 2; i++)
#pragma unroll
        for (int j = 0; j < 4; j++)
#pragma unroll
            for (int c = 0; c < 4; c++) {
                const int u   = (i * 4 + j) * 4 + c;
                const int col = warpN * 32 + j * 8 + tig * 2 + (c & 1);
                const float v = X[1][u] + bias[128 + col] + Hc[u] + bias[384 + 128 + col];
                X[1][u] = sigmoidf_fast(v);          // r gate
            }

    // ---- GEMM 2 chunk z (U q=0), stages 8,9 ----
#pragma unroll
    for (int u = 0; u < 32; u++) Hc[u] = 0.f;
    STAGE(8, Hc, false)
    STAGE(9, Hc, false)
#pragma unroll
    for (int i = 0; i < 2; i++)
#pragma unroll
        for (int j = 0; j < 4; j++)
#pragma unroll
            for (int c = 0; c < 4; c++) {
                const int u   = (i * 4 + j) * 4 + c;
                const int col = warpN * 32 + j * 8 + tig * 2 + (c & 1);
                const float v = X[0][u] + bias[col] + Hc[u] + bias[384 + col];
                X[0][u] = sigmoidf_fast(v);          // z gate
            }

    // ---- GEMM 2 chunk hh (U q=2), stages 10,11 + final combine ----
#pragma unroll
    for (int u = 0; u < 32; u++) Hc[u] = 0.f;
    STAGE(10, Hc, false)
    STAGE(11, Hc, false)
#pragma unroll
    for (int i = 0; i < 2; i++)
#pragma unroll
        for (int j = 0; j < 4; j++)
#pragma unroll
            for (int c = 0; c < 4; c++) {
                const int u   = (i * 4 + j) * 4 + c;
                const int rt  = warpM * 32 + i * 16 + gID + ((c >> 1) << 3);
                const int col = warpN * 32 + j * 8 + tig * 2 + (c & 1);
                const float rh = Hc[u] + bias[384 + 256 + col];
                const float hh = tanh_safe(X[2][u] + bias[256 + col] + X[1][u] * rh);
                const float z  = X[0][u];
                const float h  = sA2[rt * SA_PAD + col];   // exact fp32 h
                out[(size_t)(row0 + rt) * DD + col] = z * h + (1.0f - z) * hh;
            }
}

// ---------------------------------------------------------------------------
// launch
// ---------------------------------------------------------------------------
extern "C" void kernel_launch(void* const* d_in, const int* in_sizes, int n_in,
                              void* d_out, int out_size) {
    const float* atom_state = (const float*)d_in[0];
    const float* messages   = (const float*)d_in[1];
    const int*   conn       = (const int*)d_in[2];
    const float* Wk         = (const float*)d_in[3];
    const float* Uk         = (const float*)d_in[4];
    const float* bias       = (const float*)d_in[5];
    float*       out        = (float*)d_out;
    (void)in_sizes; (void)n_in; (void)out_size;

    cudaFuncSetAttribute(fused_gru_kernel,
                         cudaFuncAttributeMaxDynamicSharedMemorySize, SMEM_BYTES);

    void* agg_ptr = nullptr;
    cudaGetSymbolAddress(&agg_ptr, g_agg);
    cudaMemsetAsync(agg_ptr, 0, (size_t)MM * DD * sizeof(float));

    convert_B_kernel<<<96, 256>>>(Wk, Uk);
    scatter_kernel<<<NEDGE / 8, 256>>>(messages, conn);
    fused_gru_kernel<<<MM / 64, 256, SMEM_BYTES>>>(atom_state, bias, out);
}